// round 4
// baseline (speedup 1.0000x reference)
#include <cuda_runtime.h>
#include <cuda_bf16.h>
#include <math.h>

#define B_      2
#define S_      1536
#define DIM_    1024
#define HEADS_  16
#define HD_     64
#define BLK_    24
#define M_TOT   (B_ * S_)          // 3072
#define NBLK    (S_ / BLK_)        // 64

// ---------------- scratch (static __device__ arrays: allowed) ----------------
__device__ float g_Q[M_TOT * DIM_];
__device__ float g_K[M_TOT * DIM_];
__device__ float g_V[M_TOT * DIM_];
__device__ float g_A[M_TOT * DIM_];

// ---------------- fp32 GEMM body: C[3072,1024] = A @ W + bias ---------------
// BM=BN=128, BK=16, 256 threads, 8x8 microtile, 2-stage smem double buffer.
__device__ __forceinline__ void gemm_body(
    const float* __restrict__ A, const float* __restrict__ W,
    const float* __restrict__ bias, float* __restrict__ C)
{
    __shared__ float As[2][16][128];   // [stage][k][m]
    __shared__ float Bs[2][16][128];   // [stage][k][n]

    const int tid = threadIdx.x;
    const int tx = tid & 15;        // n-group (8 cols each)
    const int ty = tid >> 4;        // m-group (8 rows each)
    const int m0 = blockIdx.y * 128;
    const int n0 = blockIdx.x * 128;

    const int arow = tid >> 2, ac4 = tid & 3;     // A: 64 rows/pass x 4 float4
    const int brow = tid >> 5, bc4 = tid & 31;    // B: 8 rows/pass x 32 float4

    const float* Aptr = A + (size_t)m0 * DIM_;
    const float* Wptr = W + n0;

    float acc[8][8];
    #pragma unroll
    for (int i = 0; i < 8; i++)
        #pragma unroll
        for (int j = 0; j < 8; j++) acc[i][j] = 0.f;

    // ---- prologue: load slab 0 into stage 0
    {
        #pragma unroll
        for (int h = 0; h < 2; h++) {
            int r = arow + h * 64;
            float4 av = *(const float4*)&Aptr[(size_t)r * DIM_ + ac4 * 4];
            As[0][ac4 * 4 + 0][r] = av.x;
            As[0][ac4 * 4 + 1][r] = av.y;
            As[0][ac4 * 4 + 2][r] = av.z;
            As[0][ac4 * 4 + 3][r] = av.w;
        }
        #pragma unroll
        for (int h = 0; h < 2; h++) {
            int r = brow + h * 8;
            *(float4*)&Bs[0][r][bc4 * 4] = *(const float4*)&Wptr[(size_t)r * DIM_ + bc4 * 4];
        }
    }
    __syncthreads();

    int stage = 0;
    for (int k0 = 0; k0 < DIM_; k0 += 16) {
        // ---- prefetch next slab into registers (no smem conflict with compute)
        float4 pa[2], pb[2];
        const bool has_next = (k0 + 16) < DIM_;
        if (has_next) {
            int kn = k0 + 16;
            #pragma unroll
            for (int h = 0; h < 2; h++) {
                int r = arow + h * 64;
                pa[h] = *(const float4*)&Aptr[(size_t)r * DIM_ + kn + ac4 * 4];
            }
            #pragma unroll
            for (int h = 0; h < 2; h++) {
                int r = brow + h * 8;
                pb[h] = *(const float4*)&Wptr[(size_t)(kn + r) * DIM_ + bc4 * 4];
            }
        }

        // ---- compute on current stage
        #pragma unroll
        for (int k = 0; k < 16; k++) {
            float a[8], b[8];
            *(float4*)&a[0] = *(const float4*)&As[stage][k][ty * 8];
            *(float4*)&a[4] = *(const float4*)&As[stage][k][ty * 8 + 4];
            *(float4*)&b[0] = *(const float4*)&Bs[stage][k][tx * 8];
            *(float4*)&b[4] = *(const float4*)&Bs[stage][k][tx * 8 + 4];
            #pragma unroll
            for (int i = 0; i < 8; i++)
                #pragma unroll
                for (int j = 0; j < 8; j++)
                    acc[i][j] += a[i] * b[j];
        }

        // ---- store prefetched slab into other stage
        if (has_next) {
            int ns = stage ^ 1;
            #pragma unroll
            for (int h = 0; h < 2; h++) {
                int r = arow + h * 64;
                As[ns][ac4 * 4 + 0][r] = pa[h].x;
                As[ns][ac4 * 4 + 1][r] = pa[h].y;
                As[ns][ac4 * 4 + 2][r] = pa[h].z;
                As[ns][ac4 * 4 + 3][r] = pa[h].w;
            }
            #pragma unroll
            for (int h = 0; h < 2; h++) {
                int r = brow + h * 8;
                *(float4*)&Bs[ns][r][bc4 * 4] = pb[h];
            }
            __syncthreads();
            stage = ns;
        }
    }

    float bvv[8];
    *(float4*)&bvv[0] = *(const float4*)&bias[n0 + tx * 8];
    *(float4*)&bvv[4] = *(const float4*)&bias[n0 + tx * 8 + 4];
    #pragma unroll
    for (int i = 0; i < 8; i++) {
        int row = m0 + ty * 8 + i;
        float4 o0, o1;
        o0.x = acc[i][0] + bvv[0]; o0.y = acc[i][1] + bvv[1];
        o0.z = acc[i][2] + bvv[2]; o0.w = acc[i][3] + bvv[3];
        o1.x = acc[i][4] + bvv[4]; o1.y = acc[i][5] + bvv[5];
        o1.z = acc[i][6] + bvv[6]; o1.w = acc[i][7] + bvv[7];
        *(float4*)&C[(size_t)row * DIM_ + n0 + tx * 8]     = o0;
        *(float4*)&C[(size_t)row * DIM_ + n0 + tx * 8 + 4] = o1;
    }
}

// Fused QKV: blockIdx.z selects projection; scratch referenced by symbol.
__global__ __launch_bounds__(256) void gemm_qkv(
    const float* __restrict__ x,
    const float* __restrict__ Wq, const float* __restrict__ bq,
    const float* __restrict__ Wk, const float* __restrict__ bk,
    const float* __restrict__ Wv, const float* __restrict__ bv)
{
    const float* W; const float* b; float* C;
    switch (blockIdx.z) {
        case 0:  W = Wq; b = bq; C = g_Q; break;
        case 1:  W = Wk; b = bk; C = g_K; break;
        default: W = Wv; b = bv; C = g_V; break;
    }
    gemm_body(x, W, b, C);
}

__global__ __launch_bounds__(256) void gemm_out(
    const float* __restrict__ Wo, const float* __restrict__ bo,
    float* __restrict__ out)
{
    gemm_body(g_A, Wo, bo, out);
}

// ---------------- block-banded attention with fused partial RoPE ------------
// One CTA per (q-block, head, batch). Band = key blocks [qb-1, qb+1].
// RoPE (head 0 only) is applied in smem after staging Q/K.
__global__ __launch_bounds__(128) void attn_kernel(const int* __restrict__ pos)
{
    const int qb = blockIdx.x;   // 0..63
    const int h  = blockIdx.y;   // 0..15
    const int b  = blockIdx.z;   // 0..1
    const int kb0 = qb > 0 ? qb - 1 : 0;
    const int kb1 = qb < NBLK - 1 ? qb + 1 : NBLK - 1;
    const int ks  = kb0 * BLK_;
    const int nk  = (kb1 - kb0 + 1) * BLK_;   // 48 or 72
    const int q0  = qb * BLK_;

    __shared__ float Qs[24][64];
    __shared__ float Ks[72][68];   // padded rows, float4-aligned (272B)
    __shared__ float Ps[24][72];

    const int tid = threadIdx.x;   // 128 threads

    for (int e = tid; e < 24 * 64; e += 128) {
        int r = e >> 6, d = e & 63;
        Qs[r][d] = g_Q[((size_t)(b * S_ + q0 + r) * HEADS_ + h) * HD_ + d];
    }
    for (int e = tid; e < nk * 64; e += 128) {
        int r = e >> 6, d = e & 63;
        Ks[r][d] = g_K[((size_t)(b * S_ + ks + r) * HEADS_ + h) * HD_ + d];
    }
    __syncthreads();

    // Partial RoPE: only head 0. Branch is uniform across the CTA (h=blockIdx.y).
    if (h == 0) {
        for (int e = tid; e < (24 + nk) * 32; e += 128) {
            int row = e >> 5, i = e & 31;          // pair index i = 0..31
            double inv = pow(10000.0, -(double)(2 * i) / 64.0);
            bool isQ = row < 24;
            int r = isQ ? row : row - 24;
            int p = isQ ? pos[q0 + r] : pos[ks + r];
            float ang = (float)((double)p * inv);
            float c = cosf(ang), sn = sinf(ang);
            float* base = isQ ? &Qs[r][0] : &Ks[r][0];
            float v0 = base[2 * i], v1 = base[2 * i + 1];
            base[2 * i]     = v0 * c - v1 * sn;
            base[2 * i + 1] = v1 * c + v0 * sn;
        }
        __syncthreads();
    }

    const float scale = 0.125f;    // 1/sqrt(64)
    for (int e = tid; e < 24 * nk; e += 128) {
        int r = e / nk, j = e - r * nk;
        const float4* qr = (const float4*)Qs[r];
        const float4* kr = (const float4*)Ks[j];
        float acc = 0.f;
        #pragma unroll
        for (int d4 = 0; d4 < 16; d4++) {
            float4 a = qr[d4], bb = kr[d4];
            acc += a.x * bb.x + a.y * bb.y + a.z * bb.z + a.w * bb.w;
        }
        Ps[r][j] = acc * scale;
    }
    __syncthreads();

    if (tid < 24) {
        float mx = -1e30f;
        for (int j = 0; j < nk; j++) mx = fmaxf(mx, Ps[tid][j]);
        float sum = 0.f;
        for (int j = 0; j < nk; j++) {
            float e2 = expf(Ps[tid][j] - mx);
            Ps[tid][j] = e2;
            sum += e2;
        }
        float invs = 1.0f / sum;
        for (int j = 0; j < nk; j++) Ps[tid][j] *= invs;
    }
    __syncthreads();

    for (int e = tid; e < 24 * 64; e += 128) {
        int r = e >> 6, d = e & 63;
        float acc = 0.f;
        #pragma unroll 4
        for (int j = 0; j < nk; j++)
            acc += Ps[r][j] * g_V[((size_t)(b * S_ + ks + j) * HEADS_ + h) * HD_ + d];
        g_A[((size_t)(b * S_ + q0 + r) * HEADS_ + h) * HD_ + d] = acc;
    }
}

// ---------------- launch (kernel launches ONLY — capture-safe) ---------------
extern "C" void kernel_launch(void* const* d_in, const int* in_sizes, int n_in,
                              void* d_out, int out_size)
{
    const float* x  = (const float*)d_in[0];
    const float* Wq = (const float*)d_in[1];
    const float* bq = (const float*)d_in[2];
    const float* Wk = (const float*)d_in[3];
    const float* bk = (const float*)d_in[4];
    const float* Wv = (const float*)d_in[5];
    const float* bv = (const float*)d_in[6];
    const float* Wo = (const float*)d_in[7];
    const float* bo = (const float*)d_in[8];
    const int*  pos = (const int*)d_in[9];
    float* out = (float*)d_out;

    dim3 gqkv(DIM_ / 128, M_TOT / 128, 3);   // 8 x 24 x 3
    gemm_qkv<<<gqkv, 256>>>(x, Wq, bq, Wk, bk, Wv, bv);

    attn_kernel<<<dim3(NBLK, HEADS_, B_), 128>>>(pos);

    dim3 go(DIM_ / 128, M_TOT / 128);
    gemm_out<<<go, 256>>>(Wo, bo, out);
}

// round 6
// speedup vs baseline: 1.5700x; 1.5700x over previous
#include <cuda_runtime.h>
#include <cuda_bf16.h>
#include <math.h>

#define B_      2
#define S_      1536
#define DIM_    1024
#define HEADS_  16
#define HD_     64
#define BLK_    24
#define M_TOT   (B_ * S_)          // 3072
#define NBLK    (S_ / BLK_)        // 64

#define SA 40                      // As row stride (bf16 elems), 80B rows
#define SB 136                     // Bs row stride (bf16 elems), 272B rows

// ---------------- scratch (static __device__ arrays: allowed) ----------------
__device__ float g_Q[M_TOT * DIM_];
__device__ float g_K[M_TOT * DIM_];
__device__ float g_V[M_TOT * DIM_];
__device__ float g_A[M_TOT * DIM_];

// ---------------- PTX helpers ------------------------------------------------
__device__ __forceinline__ void ldsm4(unsigned* r, const __nv_bfloat16* p) {
    unsigned addr = (unsigned)__cvta_generic_to_shared(p);
    asm volatile("ldmatrix.sync.aligned.m8n8.x4.shared.b16 {%0,%1,%2,%3}, [%4];"
                 : "=r"(r[0]), "=r"(r[1]), "=r"(r[2]), "=r"(r[3]) : "r"(addr));
}
__device__ __forceinline__ void ldsm2t(unsigned* r, const __nv_bfloat16* p) {
    unsigned addr = (unsigned)__cvta_generic_to_shared(p);
    asm volatile("ldmatrix.sync.aligned.m8n8.x2.trans.shared.b16 {%0,%1}, [%2];"
                 : "=r"(r[0]), "=r"(r[1]) : "r"(addr));
}
__device__ __forceinline__ void mma16816(float* d, const unsigned* a, const unsigned* b) {
    asm volatile("mma.sync.aligned.m16n8k16.row.col.f32.bf16.bf16.f32 "
                 "{%0,%1,%2,%3},{%4,%5,%6,%7},{%8,%9},{%0,%1,%2,%3};"
                 : "+f"(d[0]), "+f"(d[1]), "+f"(d[2]), "+f"(d[3])
                 : "r"(a[0]), "r"(a[1]), "r"(a[2]), "r"(a[3]), "r"(b[0]), "r"(b[1]));
}

// Split fp32 pair -> hi/lo bf16x2 and store
__device__ __forceinline__ void st_split2(__nv_bfloat16* hi, __nv_bfloat16* lo,
                                          float x, float y) {
    __nv_bfloat16 hx = __float2bfloat16_rn(x);
    __nv_bfloat16 hy = __float2bfloat16_rn(y);
    __nv_bfloat16 lx = __float2bfloat16_rn(x - __bfloat162float(hx));
    __nv_bfloat16 ly = __float2bfloat16_rn(y - __bfloat162float(hy));
    *(__nv_bfloat162*)hi = __halves2bfloat162(hx, hy);
    *(__nv_bfloat162*)lo = __halves2bfloat162(lx, ly);
}

// ---------------- tensor-core GEMM body: C[3072,1024] = A@W + bias -----------
// CTA 128x128, BK=32, 8 warps (2x4), warp tile 64x32, bf16 split (hi/lo):
// accumulates hi*hi + lo*hi + hi*lo in fp32 (drops lo*lo ~2^-36).
__device__ __forceinline__ void gemm_body_tc(
    const float* __restrict__ A, const float* __restrict__ W,
    const float* __restrict__ bias, float* __restrict__ C)
{
    __shared__ __nv_bfloat16 Ah[128 * SA], Al[128 * SA];
    __shared__ __nv_bfloat16 Bh[32 * SB],  Bl[32 * SB];

    const int tid  = threadIdx.x;
    const int lane = tid & 31;
    const int wid  = tid >> 5;
    const int wm   = (wid & 1) * 64;    // warp m offset in tile
    const int wn   = (wid >> 1) * 32;   // warp n offset in tile
    const int m0   = blockIdx.y * 128;
    const int n0   = blockIdx.x * 128;

    const int la_m = tid >> 3, la_c = (tid & 7) * 4;    // A loader
    const int lb_k = tid >> 5, lb_c = (tid & 31) * 4;   // B loader

    const float* Abase = A + (size_t)m0 * DIM_;
    const float* Wbase = W + n0;

    float acc[16][4];
    #pragma unroll
    for (int i = 0; i < 16; i++)
        #pragma unroll
        for (int j = 0; j < 4; j++) acc[i][j] = 0.f;

    float4 ra[4], rb[4];
    #pragma unroll
    for (int i = 0; i < 4; i++)
        ra[i] = *(const float4*)&Abase[(size_t)(la_m + i * 32) * DIM_ + la_c];
    #pragma unroll
    for (int i = 0; i < 4; i++)
        rb[i] = *(const float4*)&Wbase[(size_t)(lb_k + i * 8) * DIM_ + lb_c];

    for (int k0 = 0; k0 < DIM_; k0 += 32) {
        __syncthreads();   // previous chunk's mma done
        #pragma unroll
        for (int i = 0; i < 4; i++) {
            int m = la_m + i * 32;
            float4 v = ra[i];
            st_split2(&Ah[m * SA + la_c],     &Al[m * SA + la_c],     v.x, v.y);
            st_split2(&Ah[m * SA + la_c + 2], &Al[m * SA + la_c + 2], v.z, v.w);
        }
        #pragma unroll
        for (int i = 0; i < 4; i++) {
            int k = lb_k + i * 8;
            float4 v = rb[i];
            st_split2(&Bh[k * SB + lb_c],     &Bl[k * SB + lb_c],     v.x, v.y);
            st_split2(&Bh[k * SB + lb_c + 2], &Bl[k * SB + lb_c + 2], v.z, v.w);
        }
        __syncthreads();

        if (k0 + 32 < DIM_) {   // prefetch next chunk (overlaps mma below)
            int kn = k0 + 32;
            #pragma unroll
            for (int i = 0; i < 4; i++)
                ra[i] = *(const float4*)&Abase[(size_t)(la_m + i * 32) * DIM_ + kn + la_c];
            #pragma unroll
            for (int i = 0; i < 4; i++)
                rb[i] = *(const float4*)&Wbase[(size_t)(kn + lb_k + i * 8) * DIM_ + lb_c];
        }

        #pragma unroll
        for (int ks = 0; ks < 32; ks += 16) {
            unsigned ah[4][4], al[4][4], b[4][2];
            const int arow = lane & 15;
            const int acol = ks + (lane >> 4) * 8;
            const int brow = ks + (lane & 15);

            // load A hi+lo fragments once, keep resident
            #pragma unroll
            for (int mi = 0; mi < 4; mi++) ldsm4(ah[mi], &Ah[(wm + mi * 16 + arow) * SA + acol]);
            #pragma unroll
            for (int mi = 0; mi < 4; mi++) ldsm4(al[mi], &Al[(wm + mi * 16 + arow) * SA + acol]);

            // pass 1+2: (hi + lo) * B_hi
            #pragma unroll
            for (int ni = 0; ni < 4; ni++) ldsm2t(b[ni], &Bh[brow * SB + wn + ni * 8]);
            #pragma unroll
            for (int mi = 0; mi < 4; mi++)
                #pragma unroll
                for (int ni = 0; ni < 4; ni++) mma16816(acc[mi * 4 + ni], ah[mi], b[ni]);
            #pragma unroll
            for (int mi = 0; mi < 4; mi++)
                #pragma unroll
                for (int ni = 0; ni < 4; ni++) mma16816(acc[mi * 4 + ni], al[mi], b[ni]);

            // pass 3: hi * B_lo (A_hi still in registers)
            #pragma unroll
            for (int ni = 0; ni < 4; ni++) ldsm2t(b[ni], &Bl[brow * SB + wn + ni * 8]);
            #pragma unroll
            for (int mi = 0; mi < 4; mi++)
                #pragma unroll
                for (int ni = 0; ni < 4; ni++) mma16816(acc[mi * 4 + ni], ah[mi], b[ni]);
        }
    }

    // epilogue: c0,c1 at (r, c..c+1), c2,c3 at (r+8, c..c+1)
    #pragma unroll
    for (int ni = 0; ni < 4; ni++) {
        int c = n0 + wn + ni * 8 + (lane & 3) * 2;
        float2 bv = *(const float2*)&bias[c];
        #pragma unroll
        for (int mi = 0; mi < 4; mi++) {
            const float* d = acc[mi * 4 + ni];
            int r0 = m0 + wm + mi * 16 + (lane >> 2);
            float2 v0 = {d[0] + bv.x, d[1] + bv.y};
            float2 v1 = {d[2] + bv.x, d[3] + bv.y};
            *(float2*)&C[(size_t)r0 * DIM_ + c]       = v0;
            *(float2*)&C[(size_t)(r0 + 8) * DIM_ + c] = v1;
        }
    }
}

__global__ __launch_bounds__(256, 2) void gemm_qkv(
    const float* __restrict__ x,
    const float* __restrict__ Wq, const float* __restrict__ bq,
    const float* __restrict__ Wk, const float* __restrict__ bk,
    const float* __restrict__ Wv, const float* __restrict__ bv)
{
    const float* W; const float* b; float* C;
    switch (blockIdx.z) {
        case 0:  W = Wq; b = bq; C = g_Q; break;
        case 1:  W = Wk; b = bk; C = g_K; break;
        default: W = Wv; b = bv; C = g_V; break;
    }
    gemm_body_tc(x, W, b, C);
}

__global__ __launch_bounds__(256, 2) void gemm_out(
    const float* __restrict__ Wo, const float* __restrict__ bo,
    float* __restrict__ out)
{
    gemm_body_tc(g_A, Wo, bo, out);
}

// ---------------- block-banded attention with fused partial RoPE ------------
__global__ __launch_bounds__(128) void attn_kernel(const int* __restrict__ pos)
{
    const int qb = blockIdx.x;
    const int h  = blockIdx.y;
    const int b  = blockIdx.z;
    const int kb0 = qb > 0 ? qb - 1 : 0;
    const int kb1 = qb < NBLK - 1 ? qb + 1 : NBLK - 1;
    const int ks  = kb0 * BLK_;
    const int nk  = (kb1 - kb0 + 1) * BLK_;   // 48 or 72
    const int q0  = qb * BLK_;

    __shared__ float Qs[24][64];
    __shared__ float Ks[72][68];
    __shared__ float Ps[24][72];

    const int tid = threadIdx.x;

    for (int e = tid; e < 24 * 64; e += 128) {
        int r = e >> 6, d = e & 63;
        Qs[r][d] = g_Q[((size_t)(b * S_ + q0 + r) * HEADS_ + h) * HD_ + d];
    }
    for (int e = tid; e < nk * 64; e += 128) {
        int r = e >> 6, d = e & 63;
        Ks[r][d] = g_K[((size_t)(b * S_ + ks + r) * HEADS_ + h) * HD_ + d];
    }
    __syncthreads();

    if (h == 0) {   // partial RoPE: head 0 only (uniform branch)
        for (int e = tid; e < (24 + nk) * 32; e += 128) {
            int row = e >> 5, i = e & 31;
            double inv = pow(10000.0, -(double)(2 * i) / 64.0);
            bool isQ = row < 24;
            int r = isQ ? row : row - 24;
            int p = isQ ? pos[q0 + r] : pos[ks + r];
            float ang = (float)((double)p * inv);
            float c = cosf(ang), sn = sinf(ang);
            float* base = isQ ? &Qs[r][0] : &Ks[r][0];
            float v0 = base[2 * i], v1 = base[2 * i + 1];
            base[2 * i]     = v0 * c - v1 * sn;
            base[2 * i + 1] = v1 * c + v0 * sn;
        }
        __syncthreads();
    }

    const float scale = 0.125f;
    for (int e = tid; e < 24 * nk; e += 128) {
        int r = e / nk, j = e - r * nk;
        const float4* qr = (const float4*)Qs[r];
        const float4* kr = (const float4*)Ks[j];
        float acc = 0.f;
        #pragma unroll
        for (int d4 = 0; d4 < 16; d4++) {
            float4 a = qr[d4], bb = kr[d4];
            acc += a.x * bb.x + a.y * bb.y + a.z * bb.z + a.w * bb.w;
        }
        Ps[r][j] = acc * scale;
    }
    __syncthreads();

    if (tid < 24) {
        float mx = -1e30f;
        for (int j = 0; j < nk; j++) mx = fmaxf(mx, Ps[tid][j]);
        float sum = 0.f;
        for (int j = 0; j < nk; j++) {
            float e2 = expf(Ps[tid][j] - mx);
            Ps[tid][j] = e2;
            sum += e2;
        }
        float invs = 1.0f / sum;
        for (int j = 0; j < nk; j++) Ps[tid][j] *= invs;
    }
    __syncthreads();

    for (int e = tid; e < 24 * 64; e += 128) {
        int r = e >> 6, d = e & 63;
        float acc = 0.f;
        #pragma unroll 4
        for (int j = 0; j < nk; j++)
            acc += Ps[r][j] * g_V[((size_t)(b * S_ + ks + j) * HEADS_ + h) * HD_ + d];
        g_A[((size_t)(b * S_ + q0 + r) * HEADS_ + h) * HD_ + d] = acc;
    }
}

// ---------------- launch (kernel launches ONLY — capture-safe) ---------------
extern "C" void kernel_launch(void* const* d_in, const int* in_sizes, int n_in,
                              void* d_out, int out_size)
{
    const float* x  = (const float*)d_in[0];
    const float* Wq = (const float*)d_in[1];
    const float* bq = (const float*)d_in[2];
    const float* Wk = (const float*)d_in[3];
    const float* bk = (const float*)d_in[4];
    const float* Wv = (const float*)d_in[5];
    const float* bv = (const float*)d_in[6];
    const float* Wo = (const float*)d_in[7];
    const float* bo = (const float*)d_in[8];
    const int*  pos = (const int*)d_in[9];
    float* out = (float*)d_out;

    dim3 gqkv(DIM_ / 128, M_TOT / 128, 3);   // 8 x 24 x 3
    gemm_qkv<<<gqkv, 256>>>(x, Wq, bq, Wk, bk, Wv, bv);

    attn_kernel<<<dim3(NBLK, HEADS_, B_), 128>>>(pos);

    dim3 go(DIM_ / 128, M_TOT / 128);
    gemm_out<<<go, 256>>>(Wo, bo, out);
}

// round 8
// speedup vs baseline: 1.9343x; 1.2320x over previous
#include <cuda_runtime.h>
#include <cuda_bf16.h>
#include <math.h>

#define B_      2
#define S_      1536
#define DIM_    1024
#define HEADS_  16
#define HD_     64
#define BLK_    24
#define M_TOT   (B_ * S_)          // 3072
#define NBLK    (S_ / BLK_)        // 64

#define SA 40                      // As row stride (bf16 elems), 80B rows
#define SB 136                     // Bs row stride (bf16 elems), 272B rows

// ---------------- scratch (static __device__ arrays: allowed) ----------------
__device__ float g_Q[M_TOT * DIM_];
__device__ float g_K[M_TOT * DIM_];
__device__ float g_V[M_TOT * DIM_];
__device__ float g_A[M_TOT * DIM_];

// ---------------- PTX helpers ------------------------------------------------
__device__ __forceinline__ void ldsm4(unsigned* r, const __nv_bfloat16* p) {
    unsigned addr = (unsigned)__cvta_generic_to_shared(p);
    asm volatile("ldmatrix.sync.aligned.m8n8.x4.shared.b16 {%0,%1,%2,%3}, [%4];"
                 : "=r"(r[0]), "=r"(r[1]), "=r"(r[2]), "=r"(r[3]) : "r"(addr));
}
__device__ __forceinline__ void ldsm2t(unsigned* r, const __nv_bfloat16* p) {
    unsigned addr = (unsigned)__cvta_generic_to_shared(p);
    asm volatile("ldmatrix.sync.aligned.m8n8.x2.trans.shared.b16 {%0,%1}, [%2];"
                 : "=r"(r[0]), "=r"(r[1]) : "r"(addr));
}
__device__ __forceinline__ void mma16816(float* d, const unsigned* a, const unsigned* b) {
    asm volatile("mma.sync.aligned.m16n8k16.row.col.f32.bf16.bf16.f32 "
                 "{%0,%1,%2,%3},{%4,%5,%6,%7},{%8,%9},{%0,%1,%2,%3};"
                 : "+f"(d[0]), "+f"(d[1]), "+f"(d[2]), "+f"(d[3])
                 : "r"(a[0]), "r"(a[1]), "r"(a[2]), "r"(a[3]), "r"(b[0]), "r"(b[1]));
}

// Split fp32 pair -> hi/lo bf16x2 and store
__device__ __forceinline__ void st_split2(__nv_bfloat16* hi, __nv_bfloat16* lo,
                                          float x, float y) {
    __nv_bfloat16 hx = __float2bfloat16_rn(x);
    __nv_bfloat16 hy = __float2bfloat16_rn(y);
    __nv_bfloat16 lx = __float2bfloat16_rn(x - __bfloat162float(hx));
    __nv_bfloat16 ly = __float2bfloat16_rn(y - __bfloat162float(hy));
    *(__nv_bfloat162*)hi = __halves2bfloat162(hx, hy);
    *(__nv_bfloat162*)lo = __halves2bfloat162(lx, ly);
}

// ---------------- tensor-core GEMM body: C[3072,1024] = A@W + bias -----------
// CTA 128x128, BK=32, 8 warps (2x4), warp tile 64x32, bf16 split (hi/lo):
// accumulates hi*hi + lo*hi + hi*lo in fp32 (drops lo*lo ~2^-36).
__device__ __forceinline__ void gemm_body_tc(
    const float* __restrict__ A, const float* __restrict__ W,
    const float* __restrict__ bias, float* __restrict__ C)
{
    __shared__ __nv_bfloat16 Ah[128 * SA], Al[128 * SA];
    __shared__ __nv_bfloat16 Bh[32 * SB],  Bl[32 * SB];

    const int tid  = threadIdx.x;
    const int lane = tid & 31;
    const int wid  = tid >> 5;
    const int wm   = (wid & 1) * 64;    // warp m offset in tile
    const int wn   = (wid >> 1) * 32;   // warp n offset in tile
    const int m0   = blockIdx.y * 128;
    const int n0   = blockIdx.x * 128;

    const int la_m = tid >> 3, la_c = (tid & 7) * 4;    // A loader
    const int lb_k = tid >> 5, lb_c = (tid & 31) * 4;   // B loader

    const float* Abase = A + (size_t)m0 * DIM_;
    const float* Wbase = W + n0;

    float acc[16][4];
    #pragma unroll
    for (int i = 0; i < 16; i++)
        #pragma unroll
        for (int j = 0; j < 4; j++) acc[i][j] = 0.f;

    float4 ra[4], rb[4];
    #pragma unroll
    for (int i = 0; i < 4; i++)
        ra[i] = *(const float4*)&Abase[(size_t)(la_m + i * 32) * DIM_ + la_c];
    #pragma unroll
    for (int i = 0; i < 4; i++)
        rb[i] = *(const float4*)&Wbase[(size_t)(lb_k + i * 8) * DIM_ + lb_c];

    for (int k0 = 0; k0 < DIM_; k0 += 32) {
        __syncthreads();   // previous chunk's mma done
        #pragma unroll
        for (int i = 0; i < 4; i++) {
            int m = la_m + i * 32;
            float4 v = ra[i];
            st_split2(&Ah[m * SA + la_c],     &Al[m * SA + la_c],     v.x, v.y);
            st_split2(&Ah[m * SA + la_c + 2], &Al[m * SA + la_c + 2], v.z, v.w);
        }
        #pragma unroll
        for (int i = 0; i < 4; i++) {
            int k = lb_k + i * 8;
            float4 v = rb[i];
            st_split2(&Bh[k * SB + lb_c],     &Bl[k * SB + lb_c],     v.x, v.y);
            st_split2(&Bh[k * SB + lb_c + 2], &Bl[k * SB + lb_c + 2], v.z, v.w);
        }
        __syncthreads();

        if (k0 + 32 < DIM_) {   // prefetch next chunk (overlaps mma below)
            int kn = k0 + 32;
            #pragma unroll
            for (int i = 0; i < 4; i++)
                ra[i] = *(const float4*)&Abase[(size_t)(la_m + i * 32) * DIM_ + kn + la_c];
            #pragma unroll
            for (int i = 0; i < 4; i++)
                rb[i] = *(const float4*)&Wbase[(size_t)(kn + lb_k + i * 8) * DIM_ + lb_c];
        }

        #pragma unroll
        for (int ks = 0; ks < 32; ks += 16) {
            unsigned ah[4][4], al[4][4], b[4][2];
            const int arow = lane & 15;
            const int acol = ks + (lane >> 4) * 8;
            const int brow = ks + (lane & 15);

            // load A hi+lo fragments once, keep resident
            #pragma unroll
            for (int mi = 0; mi < 4; mi++) ldsm4(ah[mi], &Ah[(wm + mi * 16 + arow) * SA + acol]);
            #pragma unroll
            for (int mi = 0; mi < 4; mi++) ldsm4(al[mi], &Al[(wm + mi * 16 + arow) * SA + acol]);

            // pass 1+2: (hi + lo) * B_hi
            #pragma unroll
            for (int ni = 0; ni < 4; ni++) ldsm2t(b[ni], &Bh[brow * SB + wn + ni * 8]);
            #pragma unroll
            for (int mi = 0; mi < 4; mi++)
                #pragma unroll
                for (int ni = 0; ni < 4; ni++) mma16816(acc[mi * 4 + ni], ah[mi], b[ni]);
            #pragma unroll
            for (int mi = 0; mi < 4; mi++)
                #pragma unroll
                for (int ni = 0; ni < 4; ni++) mma16816(acc[mi * 4 + ni], al[mi], b[ni]);

            // pass 3: hi * B_lo (A_hi still in registers)
            #pragma unroll
            for (int ni = 0; ni < 4; ni++) ldsm2t(b[ni], &Bl[brow * SB + wn + ni * 8]);
            #pragma unroll
            for (int mi = 0; mi < 4; mi++)
                #pragma unroll
                for (int ni = 0; ni < 4; ni++) mma16816(acc[mi * 4 + ni], ah[mi], b[ni]);
        }
    }

    // epilogue: c0,c1 at (r, c..c+1), c2,c3 at (r+8, c..c+1)
    #pragma unroll
    for (int ni = 0; ni < 4; ni++) {
        int c = n0 + wn + ni * 8 + (lane & 3) * 2;
        float2 bv = *(const float2*)&bias[c];
        #pragma unroll
        for (int mi = 0; mi < 4; mi++) {
            const float* d = acc[mi * 4 + ni];
            int r0 = m0 + wm + mi * 16 + (lane >> 2);
            float2 v0 = {d[0] + bv.x, d[1] + bv.y};
            float2 v1 = {d[2] + bv.x, d[3] + bv.y};
            *(float2*)&C[(size_t)r0 * DIM_ + c]       = v0;
            *(float2*)&C[(size_t)(r0 + 8) * DIM_ + c] = v1;
        }
    }
}

__global__ __launch_bounds__(256, 2) void gemm_qkv(
    const float* __restrict__ x,
    const float* __restrict__ Wq, const float* __restrict__ bq,
    const float* __restrict__ Wk, const float* __restrict__ bk,
    const float* __restrict__ Wv, const float* __restrict__ bv)
{
    const float* W; const float* b; float* C;
    switch (blockIdx.z) {
        case 0:  W = Wq; b = bq; C = g_Q; break;
        case 1:  W = Wk; b = bk; C = g_K; break;
        default: W = Wv; b = bv; C = g_V; break;
    }
    gemm_body_tc(x, W, b, C);
}

__global__ __launch_bounds__(256, 2) void gemm_out(
    const float* __restrict__ Wo, const float* __restrict__ bo,
    float* __restrict__ out)
{
    gemm_body_tc(g_A, Wo, bo, out);
}

// ---------------- block-banded attention with fused partial RoPE ------------
// One CTA per (q-block, head, batch). Band = key blocks [qb-1, qb+1].
// V is staged in smem OVER the dead Q/K region (union) after QK^T; the V load
// overlaps softmax between the same barrier pair. PV is float4-vectorized LDS.
__global__ __launch_bounds__(128) void attn_kernel(const int* __restrict__ pos)
{
    const int qb = blockIdx.x;
    const int h  = blockIdx.y;
    const int b  = blockIdx.z;
    const int kb0 = qb > 0 ? qb - 1 : 0;
    const int kb1 = qb < NBLK - 1 ? qb + 1 : NBLK - 1;
    const int ks  = kb0 * BLK_;
    const int nk  = (kb1 - kb0 + 1) * BLK_;   // 48 or 72
    const int q0  = qb * BLK_;

    __shared__ union SmemU {
        struct { float Q[24][64]; float K[72][68]; } qk;   // 25728 B
        float V[72][64];                                    // 18432 B
    } u;
    __shared__ float Ps[24][72];

    const int tid = threadIdx.x;   // 128 threads

    // ---- stage Q, K (float4 loads)
    for (int e = tid; e < 24 * 16; e += 128) {
        int r = e >> 4, d4 = e & 15;
        ((float4*)u.qk.Q[r])[d4] =
            *(const float4*)&g_Q[((size_t)(b * S_ + q0 + r) * HEADS_ + h) * HD_ + d4 * 4];
    }
    for (int e = tid; e < nk * 16; e += 128) {
        int r = e >> 4, d4 = e & 15;
        ((float4*)u.qk.K[r])[d4] =
            *(const float4*)&g_K[((size_t)(b * S_ + ks + r) * HEADS_ + h) * HD_ + d4 * 4];
    }
    __syncthreads();

    // ---- partial RoPE: head 0 only (uniform branch)
    if (h == 0) {
        for (int e = tid; e < (24 + nk) * 32; e += 128) {
            int row = e >> 5, i = e & 31;
            double inv = pow(10000.0, -(double)(2 * i) / 64.0);
            bool isQ = row < 24;
            int r = isQ ? row : row - 24;
            int p = isQ ? pos[q0 + r] : pos[ks + r];
            float ang = (float)((double)p * inv);
            float c = cosf(ang), sn = sinf(ang);
            float* base = isQ ? &u.qk.Q[r][0] : &u.qk.K[r][0];
            float v0 = base[2 * i], v1 = base[2 * i + 1];
            base[2 * i]     = v0 * c - v1 * sn;
            base[2 * i + 1] = v1 * c + v0 * sn;
        }
        __syncthreads();
    }

    // ---- QK^T -> Ps
    const float scale = 0.125f;    // 1/sqrt(64)
    for (int e = tid; e < 24 * nk; e += 128) {
        int r = e / nk, j = e - r * nk;
        const float4* qr = (const float4*)u.qk.Q[r];
        const float4* kr = (const float4*)u.qk.K[j];
        float acc = 0.f;
        #pragma unroll
        for (int d4 = 0; d4 < 16; d4++) {
            float4 a = qr[d4], bb = kr[d4];
            acc += a.x * bb.x + a.y * bb.y + a.z * bb.z + a.w * bb.w;
        }
        Ps[r][j] = acc * scale;
    }
    __syncthreads();   // Q/K dead from here; Ps fully written

    // ---- overlap: V load (all threads) + softmax (threads < 24)
    for (int e = tid; e < nk * 16; e += 128) {
        int j = e >> 4, d4 = e & 15;
        ((float4*)u.V[j])[d4] =
            *(const float4*)&g_V[((size_t)(b * S_ + ks + j) * HEADS_ + h) * HD_ + d4 * 4];
    }
    if (tid < 24) {
        float mx = -1e30f;
        #pragma unroll 8
        for (int j = 0; j < nk; j++) mx = fmaxf(mx, Ps[tid][j]);
        float sum = 0.f;
        #pragma unroll 8
        for (int j = 0; j < nk; j++) {
            float e2 = __expf(Ps[tid][j] - mx);
            Ps[tid][j] = e2;
            sum += e2;
        }
        float invs = 1.0f / sum;
        #pragma unroll 8
        for (int j = 0; j < nk; j++) Ps[tid][j] *= invs;
    }
    __syncthreads();

    // ---- PV: float4 vectorized from smem
    for (int e = tid; e < 24 * 16; e += 128) {
        int r = e >> 4, d4 = e & 15;
        float4 acc = {0.f, 0.f, 0.f, 0.f};
        #pragma unroll 4
        for (int j = 0; j < nk; j++) {
            float p = Ps[r][j];
            float4 v = ((const float4*)u.V[j])[d4];
            acc.x += p * v.x; acc.y += p * v.y;
            acc.z += p * v.z; acc.w += p * v.w;
        }
        *(float4*)&g_A[((size_t)(b * S_ + q0 + r) * HEADS_ + h) * HD_ + d4 * 4] = acc;
    }
}

// ---------------- launch (kernel launches ONLY — capture-safe) ---------------
extern "C" void kernel_launch(void* const* d_in, const int* in_sizes, int n_in,
                              void* d_out, int out_size)
{
    const float* x  = (const float*)d_in[0];
    const float* Wq = (const float*)d_in[1];
    const float* bq = (const float*)d_in[2];
    const float* Wk = (const float*)d_in[3];
    const float* bk = (const float*)d_in[4];
    const float* Wv = (const float*)d_in[5];
    const float* bv = (const float*)d_in[6];
    const float* Wo = (const float*)d_in[7];
    const float* bo = (const float*)d_in[8];
    const int*  pos = (const int*)d_in[9];
    float* out = (float*)d_out;

    dim3 gqkv(DIM_ / 128, M_TOT / 128, 3);   // 8 x 24 x 3
    gemm_qkv<<<gqkv, 256>>>(x, Wq, bq, Wk, bk, Wv, bv);

    attn_kernel<<<dim3(NBLK, HEADS_, B_), 128>>>(pos);

    dim3 go(DIM_ / 128, M_TOT / 128);
    gemm_out<<<go, 256>>>(Wo, bo, out);
}

// round 10
// speedup vs baseline: 2.1519x; 1.1125x over previous
#include <cuda_runtime.h>
#include <cuda_bf16.h>
#include <math.h>

#define B_      2
#define S_      1536
#define DIM_    1024
#define HEADS_  16
#define HD_     64
#define BLK_    24
#define M_TOT   (B_ * S_)          // 3072
#define NBLK    (S_ / BLK_)        // 64

#define SA 40                      // As row stride (bf16 elems), 80B rows
#define SB 136                     // Bs row stride (bf16 elems), 272B rows

// ---------------- scratch (static __device__ arrays: allowed) ----------------
__device__ float g_Q[M_TOT * DIM_];
__device__ float g_K[M_TOT * DIM_];
__device__ float g_V[M_TOT * DIM_];

// pre-split bf16 operands
__device__ __nv_bfloat16 g_xh[M_TOT * DIM_], g_xl[M_TOT * DIM_];
__device__ __nv_bfloat16 g_Ah[M_TOT * DIM_], g_Al[M_TOT * DIM_];
__device__ __nv_bfloat16 g_Wqh[DIM_ * DIM_], g_Wql[DIM_ * DIM_];
__device__ __nv_bfloat16 g_Wkh[DIM_ * DIM_], g_Wkl[DIM_ * DIM_];
__device__ __nv_bfloat16 g_Wvh[DIM_ * DIM_], g_Wvl[DIM_ * DIM_];
__device__ __nv_bfloat16 g_Woh[DIM_ * DIM_], g_Wol[DIM_ * DIM_];

// ---------------- PTX helpers ------------------------------------------------
__device__ __forceinline__ void ldsm4(unsigned* r, const __nv_bfloat16* p) {
    unsigned addr = (unsigned)__cvta_generic_to_shared(p);
    asm volatile("ldmatrix.sync.aligned.m8n8.x4.shared.b16 {%0,%1,%2,%3}, [%4];"
                 : "=r"(r[0]), "=r"(r[1]), "=r"(r[2]), "=r"(r[3]) : "r"(addr));
}
__device__ __forceinline__ void ldsm2t(unsigned* r, const __nv_bfloat16* p) {
    unsigned addr = (unsigned)__cvta_generic_to_shared(p);
    asm volatile("ldmatrix.sync.aligned.m8n8.x2.trans.shared.b16 {%0,%1}, [%2];"
                 : "=r"(r[0]), "=r"(r[1]) : "r"(addr));
}
__device__ __forceinline__ void mma16816(float* d, const unsigned* a, const unsigned* b) {
    asm volatile("mma.sync.aligned.m16n8k16.row.col.f32.bf16.bf16.f32 "
                 "{%0,%1,%2,%3},{%4,%5,%6,%7},{%8,%9},{%0,%1,%2,%3};"
                 : "+f"(d[0]), "+f"(d[1]), "+f"(d[2]), "+f"(d[3])
                 : "r"(a[0]), "r"(a[1]), "r"(a[2]), "r"(a[3]), "r"(b[0]), "r"(b[1]));
}

// Split fp32 pair -> hi/lo bf16x2 and store
__device__ __forceinline__ void st_split2(__nv_bfloat16* hi, __nv_bfloat16* lo,
                                          float x, float y) {
    __nv_bfloat16 hx = __float2bfloat16_rn(x);
    __nv_bfloat16 hy = __float2bfloat16_rn(y);
    __nv_bfloat16 lx = __float2bfloat16_rn(x - __bfloat162float(hx));
    __nv_bfloat16 ly = __float2bfloat16_rn(y - __bfloat162float(hy));
    *(__nv_bfloat162*)hi = __halves2bfloat162(hx, hy);
    *(__nv_bfloat162*)lo = __halves2bfloat162(lx, ly);
}

// ---------------- fp32 -> bf16 hi/lo split -----------------------------------
// Destinations are __device__ globals selected INSIDE device code (host code
// must never take the address of a __device__ symbol).
__global__ __launch_bounds__(256) void split_all(
    const float* __restrict__ x,  const float* __restrict__ Wq,
    const float* __restrict__ Wk, const float* __restrict__ Wv,
    const float* __restrict__ Wo)
{
    const float* src; __nv_bfloat16* h; __nv_bfloat16* l; int n;
    switch (blockIdx.y) {
        case 0:  src = x;  h = g_xh;  l = g_xl;  n = M_TOT * DIM_; break;
        case 1:  src = Wq; h = g_Wqh; l = g_Wql; n = DIM_ * DIM_;  break;
        case 2:  src = Wk; h = g_Wkh; l = g_Wkl; n = DIM_ * DIM_;  break;
        case 3:  src = Wv; h = g_Wvh; l = g_Wvl; n = DIM_ * DIM_;  break;
        default: src = Wo; h = g_Woh; l = g_Wol; n = DIM_ * DIM_;  break;
    }
    int i = (blockIdx.x * 256 + threadIdx.x) * 4;
    if (i < n) {
        float4 v = *(const float4*)&src[i];
        st_split2(&h[i],     &l[i],     v.x, v.y);
        st_split2(&h[i + 2], &l[i + 2], v.z, v.w);
    }
}

// ---------------- tensor-core GEMM body: C[3072,1024] = A@W + bias -----------
// CTA 128x128, BK=32, 8 warps (2x4), warp tile 64x32. Operands pre-split to
// bf16 hi/lo in global; accumulates hi*hi + lo*hi + hi*lo in fp32.
__device__ __forceinline__ void gemm_body_tc(
    const __nv_bfloat16* __restrict__ Ah_g, const __nv_bfloat16* __restrict__ Al_g,
    const __nv_bfloat16* __restrict__ Wh_g, const __nv_bfloat16* __restrict__ Wl_g,
    const float* __restrict__ bias, float* __restrict__ C)
{
    __shared__ __nv_bfloat16 Ah[128 * SA], Al[128 * SA];
    __shared__ __nv_bfloat16 Bh[32 * SB],  Bl[32 * SB];

    const int tid  = threadIdx.x;
    const int lane = tid & 31;
    const int wid  = tid >> 5;
    const int wm   = (wid & 1) * 64;    // warp m offset
    const int wn   = (wid >> 1) * 32;   // warp n offset
    const int m0   = blockIdx.y * 128;
    const int n0   = blockIdx.x * 128;

    const int la_m = tid >> 3, la_c = (tid & 7) * 4;    // A: 32 rows x (8x4) cols
    const int lb_k = tid >> 5, lb_c = (tid & 31) * 4;   // B: 8 rows x (32x4) cols

    const __nv_bfloat16* Abh = Ah_g + (size_t)m0 * DIM_;
    const __nv_bfloat16* Abl = Al_g + (size_t)m0 * DIM_;
    const __nv_bfloat16* Wbh = Wh_g + n0;
    const __nv_bfloat16* Wbl = Wl_g + n0;

    float acc[16][4];
    #pragma unroll
    for (int i = 0; i < 16; i++)
        #pragma unroll
        for (int j = 0; j < 4; j++) acc[i][j] = 0.f;

    uint2 rah[4], ral[4], rbh[4], rbl[4];
    #pragma unroll
    for (int i = 0; i < 4; i++) {
        size_t off = (size_t)(la_m + i * 32) * DIM_ + la_c;
        rah[i] = *(const uint2*)&Abh[off];
        ral[i] = *(const uint2*)&Abl[off];
    }
    #pragma unroll
    for (int i = 0; i < 4; i++) {
        size_t off = (size_t)(lb_k + i * 8) * DIM_ + lb_c;
        rbh[i] = *(const uint2*)&Wbh[off];
        rbl[i] = *(const uint2*)&Wbl[off];
    }

    for (int k0 = 0; k0 < DIM_; k0 += 32) {
        __syncthreads();   // previous chunk's mma done
        #pragma unroll
        for (int i = 0; i < 4; i++) {
            int m = la_m + i * 32;
            *(uint2*)&Ah[m * SA + la_c] = rah[i];
            *(uint2*)&Al[m * SA + la_c] = ral[i];
        }
        #pragma unroll
        for (int i = 0; i < 4; i++) {
            int k = lb_k + i * 8;
            *(uint2*)&Bh[k * SB + lb_c] = rbh[i];
            *(uint2*)&Bl[k * SB + lb_c] = rbl[i];
        }
        __syncthreads();

        if (k0 + 32 < DIM_) {   // prefetch next chunk (overlaps mma below)
            int kn = k0 + 32;
            #pragma unroll
            for (int i = 0; i < 4; i++) {
                size_t off = (size_t)(la_m + i * 32) * DIM_ + kn + la_c;
                rah[i] = *(const uint2*)&Abh[off];
                ral[i] = *(const uint2*)&Abl[off];
            }
            #pragma unroll
            for (int i = 0; i < 4; i++) {
                size_t off = (size_t)(kn + lb_k + i * 8) * DIM_ + lb_c;
                rbh[i] = *(const uint2*)&Wbh[off];
                rbl[i] = *(const uint2*)&Wbl[off];
            }
        }

        #pragma unroll
        for (int ks = 0; ks < 32; ks += 16) {
            unsigned ah[4][4], al[4][4], b[4][2];
            const int arow = lane & 15;
            const int acol = ks + (lane >> 4) * 8;
            const int brow = ks + (lane & 15);

            #pragma unroll
            for (int mi = 0; mi < 4; mi++) ldsm4(ah[mi], &Ah[(wm + mi * 16 + arow) * SA + acol]);
            #pragma unroll
            for (int mi = 0; mi < 4; mi++) ldsm4(al[mi], &Al[(wm + mi * 16 + arow) * SA + acol]);

            // (A_hi + A_lo) * B_hi
            #pragma unroll
            for (int ni = 0; ni < 4; ni++) ldsm2t(b[ni], &Bh[brow * SB + wn + ni * 8]);
            #pragma unroll
            for (int mi = 0; mi < 4; mi++)
                #pragma unroll
                for (int ni = 0; ni < 4; ni++) mma16816(acc[mi * 4 + ni], ah[mi], b[ni]);
            #pragma unroll
            for (int mi = 0; mi < 4; mi++)
                #pragma unroll
                for (int ni = 0; ni < 4; ni++) mma16816(acc[mi * 4 + ni], al[mi], b[ni]);

            // A_hi * B_lo
            #pragma unroll
            for (int ni = 0; ni < 4; ni++) ldsm2t(b[ni], &Bl[brow * SB + wn + ni * 8]);
            #pragma unroll
            for (int mi = 0; mi < 4; mi++)
                #pragma unroll
                for (int ni = 0; ni < 4; ni++) mma16816(acc[mi * 4 + ni], ah[mi], b[ni]);
        }
    }

    #pragma unroll
    for (int ni = 0; ni < 4; ni++) {
        int c = n0 + wn + ni * 8 + (lane & 3) * 2;
        float2 bv = *(const float2*)&bias[c];
        #pragma unroll
        for (int mi = 0; mi < 4; mi++) {
            const float* d = acc[mi * 4 + ni];
            int r0 = m0 + wm + mi * 16 + (lane >> 2);
            float2 v0 = {d[0] + bv.x, d[1] + bv.y};
            float2 v1 = {d[2] + bv.x, d[3] + bv.y};
            *(float2*)&C[(size_t)r0 * DIM_ + c]       = v0;
            *(float2*)&C[(size_t)(r0 + 8) * DIM_ + c] = v1;
        }
    }
}

__global__ __launch_bounds__(256, 2) void gemm_qkv(
    const float* __restrict__ bq, const float* __restrict__ bk,
    const float* __restrict__ bv)
{
    switch (blockIdx.z) {
        case 0:  gemm_body_tc(g_xh, g_xl, g_Wqh, g_Wql, bq, g_Q); break;
        case 1:  gemm_body_tc(g_xh, g_xl, g_Wkh, g_Wkl, bk, g_K); break;
        default: gemm_body_tc(g_xh, g_xl, g_Wvh, g_Wvl, bv, g_V); break;
    }
}

__global__ __launch_bounds__(256, 2) void gemm_out(
    const float* __restrict__ bo, float* __restrict__ out)
{
    gemm_body_tc(g_Ah, g_Al, g_Woh, g_Wol, bo, out);
}

// ---------------- block-banded attention with fused partial RoPE ------------
// 256 threads/CTA. V staged over dead Q/K smem (union). Softmax: 8 threads/row
// with shfl reductions. Epilogue writes pre-split bf16 hi/lo for gemm_out.
__global__ __launch_bounds__(256) void attn_kernel(const int* __restrict__ pos)
{
    const int qb = blockIdx.x;
    const int h  = blockIdx.y;
    const int b  = blockIdx.z;
    const int kb0 = qb > 0 ? qb - 1 : 0;
    const int kb1 = qb < NBLK - 1 ? qb + 1 : NBLK - 1;
    const int ks  = kb0 * BLK_;
    const int nk  = (kb1 - kb0 + 1) * BLK_;   // 48 or 72
    const int q0  = qb * BLK_;

    __shared__ union SmemU {
        struct { float Q[24][64]; float K[72][68]; } qk;
        float V[72][64];
    } u;
    __shared__ float Ps[24][72];

    const int tid = threadIdx.x;   // 256 threads

    for (int e = tid; e < 24 * 16; e += 256) {
        int r = e >> 4, d4 = e & 15;
        ((float4*)u.qk.Q[r])[d4] =
            *(const float4*)&g_Q[((size_t)(b * S_ + q0 + r) * HEADS_ + h) * HD_ + d4 * 4];
    }
    for (int e = tid; e < nk * 16; e += 256) {
        int r = e >> 4, d4 = e & 15;
        ((float4*)u.qk.K[r])[d4] =
            *(const float4*)&g_K[((size_t)(b * S_ + ks + r) * HEADS_ + h) * HD_ + d4 * 4];
    }
    __syncthreads();

    if (h == 0) {   // partial RoPE: head 0 only (uniform branch per CTA)
        for (int e = tid; e < (24 + nk) * 32; e += 256) {
            int row = e >> 5, i = e & 31;
            double inv = pow(10000.0, -(double)(2 * i) / 64.0);
            bool isQ = row < 24;
            int r = isQ ? row : row - 24;
            int p = isQ ? pos[q0 + r] : pos[ks + r];
            float ang = (float)((double)p * inv);
            float c = cosf(ang), sn = sinf(ang);
            float* base = isQ ? &u.qk.Q[r][0] : &u.qk.K[r][0];
            float v0 = base[2 * i], v1 = base[2 * i + 1];
            base[2 * i]     = v0 * c - v1 * sn;
            base[2 * i + 1] = v1 * c + v0 * sn;
        }
        __syncthreads();
    }

    const float scale = 0.125f;    // 1/sqrt(64)
    for (int e = tid; e < 24 * nk; e += 256) {
        int r = e / nk, j = e - r * nk;
        const float4* qr = (const float4*)u.qk.Q[r];
        const float4* kr = (const float4*)u.qk.K[j];
        float acc = 0.f;
        #pragma unroll
        for (int d4 = 0; d4 < 16; d4++) {
            float4 a = qr[d4], bb = kr[d4];
            acc += a.x * bb.x + a.y * bb.y + a.z * bb.z + a.w * bb.w;
        }
        Ps[r][j] = acc * scale;
    }
    __syncthreads();   // Q/K dead; Ps complete

    // overlap: V load (all threads) + softmax (threads < 192, 8 per row)
    for (int e = tid; e < nk * 16; e += 256) {
        int j = e >> 4, d4 = e & 15;
        ((float4*)u.V[j])[d4] =
            *(const float4*)&g_V[((size_t)(b * S_ + ks + j) * HEADS_ + h) * HD_ + d4 * 4];
    }
    if (tid < 192) {
        const int row = tid >> 3, sub = tid & 7;
        float mx = -1e30f;
        for (int j = sub; j < nk; j += 8) mx = fmaxf(mx, Ps[row][j]);
        #pragma unroll
        for (int o = 4; o; o >>= 1) mx = fmaxf(mx, __shfl_xor_sync(0xffffffffu, mx, o));
        float sum = 0.f;
        for (int j = sub; j < nk; j += 8) {
            float e2 = __expf(Ps[row][j] - mx);
            Ps[row][j] = e2;
            sum += e2;
        }
        #pragma unroll
        for (int o = 4; o; o >>= 1) sum += __shfl_xor_sync(0xffffffffu, sum, o);
        float inv = 1.0f / sum;
        for (int j = sub; j < nk; j += 8) Ps[row][j] *= inv;
    }
    __syncthreads();

    // PV (float4 from smem) + split epilogue for gemm_out
    for (int e = tid; e < 24 * 16; e += 256) {
        int r = e >> 4, d4 = e & 15;
        float4 acc = {0.f, 0.f, 0.f, 0.f};
        #pragma unroll 4
        for (int j = 0; j < nk; j++) {
            float p = Ps[r][j];
            float4 v = ((const float4*)u.V[j])[d4];
            acc.x += p * v.x; acc.y += p * v.y;
            acc.z += p * v.z; acc.w += p * v.w;
        }
        size_t idx = ((size_t)(b * S_ + q0 + r) * HEADS_ + h) * HD_ + d4 * 4;
        st_split2(&g_Ah[idx],     &g_Al[idx],     acc.x, acc.y);
        st_split2(&g_Ah[idx + 2], &g_Al[idx + 2], acc.z, acc.w);
    }
}

// ---------------- launch (kernel launches ONLY — capture-safe) ---------------
extern "C" void kernel_launch(void* const* d_in, const int* in_sizes, int n_in,
                              void* d_out, int out_size)
{
    const float* x  = (const float*)d_in[0];
    const float* Wq = (const float*)d_in[1];
    const float* bq = (const float*)d_in[2];
    const float* Wk = (const float*)d_in[3];
    const float* bk = (const float*)d_in[4];
    const float* Wv = (const float*)d_in[5];
    const float* bv = (const float*)d_in[6];
    const float* Wo = (const float*)d_in[7];
    const float* bo = (const float*)d_in[8];
    const int*  pos = (const int*)d_in[9];
    float* out = (float*)d_out;

    // split all operands: grid.y selects tensor (0:x, 1..4: weights)
    dim3 gs(M_TOT * DIM_ / 1024, 5);   // 3072 x 5; weight blocks self-guard
    split_all<<<gs, 256>>>(x, Wq, Wk, Wv, Wo);

    dim3 gqkv(DIM_ / 128, M_TOT / 128, 3);   // 8 x 24 x 3
    gemm_qkv<<<gqkv, 256>>>(bq, bk, bv);

    attn_kernel<<<dim3(NBLK, HEADS_, B_), 256>>>(pos);

    dim3 go(DIM_ / 128, M_TOT / 128);
    gemm_out<<<go, 256>>>(bo, out);
}